// round 1
// baseline (speedup 1.0000x reference)
#include <cuda_runtime.h>
#include <cuda_bf16.h>

#define NNODE 50000
#define NEDGE 300000
#define DIM   256
#define FEATD 1024
#define NCLS  40

// ---------------- scratch (static device memory; no allocations) -------------
__device__ float g_bufA[(size_t)NNODE * DIM];   // current node features
__device__ float g_bufM[(size_t)NNODE * DIM];   // SpMM aggregation buffer
__device__ float g_norm_s[NNODE];
__device__ float g_norm_d[NNODE];
__device__ float g_deg_out[NNODE];
__device__ float g_deg_in[NNODE];
__device__ float g_sum[DIM];
__device__ float g_sumsq[DIM];
__device__ float g_scale[DIM];
__device__ float g_shift[DIM];

// ---------------- degree / norm --------------------------------------------
__global__ void k_degree(const int* __restrict__ src, const int* __restrict__ dst) {
    int e = blockIdx.x * blockDim.x + threadIdx.x;
    if (e < NEDGE) {
        atomicAdd(&g_deg_out[src[e]], 1.0f);
        atomicAdd(&g_deg_in[dst[e]], 1.0f);
    }
}

__global__ void k_norms() {
    int i = blockIdx.x * blockDim.x + threadIdx.x;
    if (i < NNODE) {
        g_norm_s[i] = rsqrtf(fmaxf(g_deg_out[i], 1.0f));
        g_norm_d[i] = rsqrtf(fmaxf(g_deg_in[i], 1.0f));
    }
}

// ---------------- SpMM: m[dst] += x[src] * norm_s[src] ----------------------
// one thread per (edge, float4-chunk); 64 chunks per row of 256 floats.
__global__ void k_spmm(const int* __restrict__ src, const int* __restrict__ dst,
                       const float* __restrict__ x, float* __restrict__ m) {
    int idx = blockIdx.x * blockDim.x + threadIdx.x;   // < NEDGE*64 (19.2M)
    if (idx >= NEDGE * 64) return;
    int e = idx >> 6;
    int c = idx & 63;
    int s = src[e];
    int d = dst[e];
    float ns = g_norm_s[s];
    float4 v = ((const float4*)x)[s * 64 + c];
    v.x *= ns; v.y *= ns; v.z *= ns; v.w *= ns;
    float4* p = ((float4*)m) + d * 64 + c;
    asm volatile("red.global.add.v4.f32 [%0], {%1,%2,%3,%4};"
                 :: "l"(p), "f"(v.x), "f"(v.y), "f"(v.z), "f"(v.w)
                 : "memory");
}

// ---------------- SGEMM: C[M,Ncol] = (A * rowscale?) @ B + bias -------------
// A row-major [M,K], B row-major [K,Ncol]. BM=BN=128, BK=8, 256 threads, 8x8/thr.
// Requires Ncol % 128 == 0 and K % 8 == 0 (true here: Ncol=256, K in {1024,256}).
__global__ __launch_bounds__(256) void k_sgemm(
    const float* __restrict__ A, const float* __restrict__ B,
    const float* __restrict__ bias, const float* __restrict__ rowscale,
    float* __restrict__ C, int M, int Ncol, int K)
{
    __shared__ float As[8][128];
    __shared__ float Bs[8][128];

    int tid = threadIdx.x;
    int tx = tid & 15;        // 0..15
    int ty = tid >> 4;        // 0..15
    int rowBase = blockIdx.y * 128;
    int colBase = blockIdx.x * 128;

    int aRow = tid >> 1;          // 0..127
    int aCol = (tid & 1) * 4;     // 0 or 4
    int bRow = tid >> 5;          // 0..7
    int bCol = (tid & 31) * 4;    // 0..124

    int gARow = rowBase + aRow;
    bool aValid = gARow < M;
    float rs = 1.0f;
    if (rowscale != nullptr && aValid) rs = rowscale[gARow];

    const float* Aptr = A + (size_t)(aValid ? gARow : 0) * K + aCol;
    const float* Bptr = B + (size_t)bRow * Ncol + colBase + bCol;

    float acc[8][8];
    #pragma unroll
    for (int i = 0; i < 8; i++)
        #pragma unroll
        for (int j = 0; j < 8; j++) acc[i][j] = 0.0f;

    for (int k0 = 0; k0 < K; k0 += 8) {
        float4 a4 = make_float4(0.f, 0.f, 0.f, 0.f);
        if (aValid) a4 = *(const float4*)(Aptr + k0);
        a4.x *= rs; a4.y *= rs; a4.z *= rs; a4.w *= rs;
        As[aCol + 0][aRow] = a4.x;
        As[aCol + 1][aRow] = a4.y;
        As[aCol + 2][aRow] = a4.z;
        As[aCol + 3][aRow] = a4.w;

        float4 b4 = *(const float4*)(Bptr + (size_t)k0 * Ncol);
        *(float4*)&Bs[bRow][bCol] = b4;

        __syncthreads();

        #pragma unroll
        for (int k = 0; k < 8; k++) {
            float af[8], bf[8];
            *(float4*)(af)     = *(float4*)&As[k][ty * 8];
            *(float4*)(af + 4) = *(float4*)&As[k][ty * 8 + 4];
            *(float4*)(bf)     = *(float4*)&Bs[k][tx * 8];
            *(float4*)(bf + 4) = *(float4*)&Bs[k][tx * 8 + 4];
            #pragma unroll
            for (int i = 0; i < 8; i++)
                #pragma unroll
                for (int j = 0; j < 8; j++)
                    acc[i][j] = fmaf(af[i], bf[j], acc[i][j]);
        }
        __syncthreads();
    }

    #pragma unroll
    for (int i = 0; i < 8; i++) {
        int r = rowBase + ty * 8 + i;
        if (r < M) {
            #pragma unroll
            for (int j = 0; j < 8; j += 4) {
                int cidx = colBase + tx * 8 + j;
                float4 o;
                o.x = acc[i][j + 0] + bias[cidx + 0];
                o.y = acc[i][j + 1] + bias[cidx + 1];
                o.z = acc[i][j + 2] + bias[cidx + 2];
                o.w = acc[i][j + 3] + bias[cidx + 3];
                *(float4*)&C[(size_t)r * Ncol + cidx] = o;
            }
        }
    }
}

// ---------------- batchnorm stats + finalize + fused bn/elu -----------------
__global__ void k_bnstats(const float* __restrict__ x) {
    int c = threadIdx.x;           // 256 threads, one column each
    float s = 0.0f, sq = 0.0f;
    for (int r = blockIdx.x; r < NNODE; r += gridDim.x) {
        float v = x[(size_t)r * DIM + c];
        s += v;
        sq += v * v;
    }
    atomicAdd(&g_sum[c], s);
    atomicAdd(&g_sumsq[c], sq);
}

__global__ void k_bnfin(const float* __restrict__ gamma, const float* __restrict__ beta) {
    int c = threadIdx.x;
    float invN = 1.0f / (float)NNODE;
    float mean = g_sum[c] * invN;
    float var  = g_sumsq[c] * invN - mean * mean;
    float sc = gamma[c] * rsqrtf(var + 1e-5f);
    g_scale[c] = sc;
    g_shift[c] = beta[c] - mean * sc;
}

__global__ void k_bnelu(float* __restrict__ x) {
    int idx = blockIdx.x * blockDim.x + threadIdx.x;   // < NNODE*64
    if (idx >= NNODE * 64) return;
    int c4 = idx & 63;
    float4 v = ((float4*)x)[idx];
    float4 sc = ((const float4*)g_scale)[c4];
    float4 sh = ((const float4*)g_shift)[c4];
    float y0 = fmaf(v.x, sc.x, sh.x);
    float y1 = fmaf(v.y, sc.y, sh.y);
    float y2 = fmaf(v.z, sc.z, sh.z);
    float y3 = fmaf(v.w, sc.w, sh.w);
    v.x = y0 > 0.f ? y0 : expm1f(y0);
    v.y = y1 > 0.f ? y1 : expm1f(y1);
    v.z = y2 > 0.f ? y2 : expm1f(y2);
    v.w = y3 > 0.f ? y3 : expm1f(y3);
    ((float4*)x)[idx] = v;
}

// ---------------- logits: out[N,40] = x[N,256] @ W[256,40] + b --------------
__global__ __launch_bounds__(256) void k_logits(
    const float* __restrict__ x, const float* __restrict__ W,
    const float* __restrict__ b, float* __restrict__ out)
{
    __shared__ float Ws[DIM * NCLS];   // 40 KB
    __shared__ float bsh[NCLS];
    int tid = threadIdx.x;
    for (int i = tid; i < DIM * NCLS; i += 256) Ws[i] = W[i];
    if (tid < NCLS) bsh[tid] = b[tid];
    __syncthreads();

    int warp = tid >> 5;
    int lane = tid & 31;
    int c1 = (lane < 8) ? lane + 32 : lane;   // valid smem index always

    for (int r = blockIdx.x * 8 + warp; r < NNODE; r += gridDim.x * 8) {
        const float* xr = x + (size_t)r * DIM;
        float acc0 = 0.0f, acc1 = 0.0f;
        #pragma unroll 8
        for (int k = 0; k < DIM; k++) {
            float xv = __ldg(xr + k);
            acc0 = fmaf(xv, Ws[k * NCLS + lane], acc0);
            acc1 = fmaf(xv, Ws[k * NCLS + c1], acc1);
        }
        out[(size_t)r * NCLS + lane] = acc0 + bsh[lane];
        if (lane < 8)
            out[(size_t)r * NCLS + lane + 32] = acc1 + bsh[lane + 32];
    }
}

// ---------------- launch ----------------------------------------------------
extern "C" void kernel_launch(void* const* d_in, const int* in_sizes, int n_in,
                              void* d_out, int out_size) {
    const float* feat  = (const float*)d_in[0];
    const int*   src   = (const int*)  d_in[1];
    const int*   dst   = (const int*)  d_in[2];
    const float* W_fc  = (const float*)d_in[3];
    const float* b_fc  = (const float*)d_in[4];
    const float* W1    = (const float*)d_in[5];
    const float* b1    = (const float*)d_in[6];
    const float* W2    = (const float*)d_in[7];
    const float* b2    = (const float*)d_in[8];
    const float* W3    = (const float*)d_in[9];
    const float* b3    = (const float*)d_in[10];
    const float* gamma = (const float*)d_in[11];
    const float* beta  = (const float*)d_in[12];
    const float* W_lin = (const float*)d_in[13];
    const float* b_lin = (const float*)d_in[14];

    float* out  = (float*)d_out;
    float* outX = out;                            // [N, 256]
    float* outL = out + (size_t)NNODE * DIM;      // [N, 40]

    float *bufA, *bufM, *norm_d, *deg_out, *deg_in, *sum, *sumsq;
    cudaGetSymbolAddress((void**)&bufA,    g_bufA);
    cudaGetSymbolAddress((void**)&bufM,    g_bufM);
    cudaGetSymbolAddress((void**)&norm_d,  g_norm_d);
    cudaGetSymbolAddress((void**)&deg_out, g_deg_out);
    cudaGetSymbolAddress((void**)&deg_in,  g_deg_in);
    cudaGetSymbolAddress((void**)&sum,     g_sum);
    cudaGetSymbolAddress((void**)&sumsq,   g_sumsq);

    // degrees & norms
    cudaMemsetAsync(deg_out, 0, NNODE * sizeof(float));
    cudaMemsetAsync(deg_in,  0, NNODE * sizeof(float));
    k_degree<<<(NEDGE + 255) / 256, 256>>>(src, dst);
    k_norms<<<(NNODE + 255) / 256, 256>>>();

    // x0 = feat @ W_fc + b_fc
    dim3 gemmGrid(DIM / 128, (NNODE + 127) / 128);
    k_sgemm<<<gemmGrid, 256>>>(feat, W_fc, b_fc, nullptr, bufA, NNODE, DIM, FEATD);

    const float* Ws[3] = {W1, W2, W3};
    const float* bs[3] = {b1, b2, b3};

    for (int l = 0; l < 3; l++) {
        // m = segment_sum((x * norm_s)[src], dst)
        cudaMemsetAsync(bufM, 0, (size_t)NNODE * DIM * sizeof(float));
        k_spmm<<<(NEDGE * 64 + 255) / 256, 256>>>(src, dst, bufA, bufM);

        // x' = (m * norm_d) @ W + b
        float* dstBuf = (l == 2) ? outX : bufA;
        k_sgemm<<<gemmGrid, 256>>>(bufM, Ws[l], bs[l], norm_d, dstBuf, NNODE, DIM, DIM);

        if (l < 2) {
            cudaMemsetAsync(sum,   0, DIM * sizeof(float));
            cudaMemsetAsync(sumsq, 0, DIM * sizeof(float));
            k_bnstats<<<512, 256>>>(bufA);
            k_bnfin<<<1, 256>>>(gamma, beta);
            k_bnelu<<<(NNODE * 64 + 255) / 256, 256>>>(bufA);
        }
    }

    // logits = x3 @ W_lin + b_lin
    k_logits<<<1024, 256>>>(outX, W_lin, b_lin, outL);
}